// round 17
// baseline (speedup 1.0000x reference)
#include <cuda_runtime.h>
#include <cuda_bf16.h>
#include <cstdint>

// Constants: B=16, C=128, T=8, BR=16, S=8, SY=64, INPUT_SIZE=16384, C*T*BR=16384
// seg_on = (count>=16 of 64), branch_on = (count>=4 of 8)
// Output = layer2 branch_on at t==0 -> (16,128,16) float32

__device__ __align__(16) uint16_t g_xbits[16384];
__device__ __align__(16) uint16_t g_act1[16384];

__device__ __forceinline__ uint32_t maj3(uint32_t a, uint32_t b, uint32_t c) {
    return (a & b) | (a & c) | (b & c);
}

#define SHFLX(v, m) __shfl_xor_sync(0xffffffffu, (v), (m))

__device__ __forceinline__ uint32_t smem_u32(const void* p) {
    uint32_t a;
    asm("{ .reg .u64 t; cvta.to.shared.u64 t, %1; cvt.u32.u64 %0, t; }"
        : "=r"(a) : "l"(p));
    return a;
}

__device__ __forceinline__ void mbar_wait(uint32_t mbar, uint32_t parity) {
    asm volatile(
        "{\n\t"
        ".reg .pred P;\n\t"
        "W_%=:\n\t"
        "mbarrier.try_wait.parity.shared::cta.b64 P, [%0], %1;\n\t"
        "@!P bra W_%=;\n\t"
        "}" :: "r"(mbar), "r"(parity) : "memory");
}

// Issue-side of the 32KB global->shared bulk copy (TMA). Wait is separate so
// the caller can overlap independent loads with the fill.
__device__ __forceinline__ void bulk_fill_issue(uint16_t* sx, const void* gsrc,
                                                uint32_t mbar) {
    if (threadIdx.x == 0) {
        asm volatile("mbarrier.arrive.expect_tx.shared::cta.b64 _, [%0], %1;"
                     :: "r"(mbar), "r"(32768u) : "memory");
        uint32_t dst = smem_u32(sx + 8);
        asm volatile(
            "cp.async.bulk.shared::cluster.global.mbarrier::complete_tx::bytes "
            "[%0], [%1], %2, [%3];"
            :: "r"(dst), "l"(gsrc), "r"(32768u), "r"(mbar) : "memory");
    }
    if (threadIdx.x < 8) sx[threadIdx.x] = 0;   // slots 0..7 (idx==-1 -> slot 7)
}

// Dual branch mask (proven): lane gets 4 int4 of branch A, 4 of branch B.
// Lane L owns segment L>>2, quarter L&3. Returns on ALL lanes:
// lo16 = branch_on batch mask of A, hi16 = of B.
__device__ __forceinline__ uint32_t branch_mask_dual(
    const int4* A, const int4* E, const uint16_t* __restrict__ sx) {
    int4 a0 = A[0], a1 = A[1], a2 = A[2], a3 = A[3];
    int4 e0 = E[0], e1 = E[1], e2 = E[2], e3 = E[3];
#define LK(v) ((uint32_t)sx[(v) + 8])
    uint32_t m0 = LK(a0.x) | (LK(e0.x) << 16), m1 = LK(a0.y) | (LK(e0.y) << 16);
    uint32_t m2 = LK(a0.z) | (LK(e0.z) << 16), m3 = LK(a0.w) | (LK(e0.w) << 16);
    uint32_t m4 = LK(a1.x) | (LK(e1.x) << 16), m5 = LK(a1.y) | (LK(e1.y) << 16);
    uint32_t m6 = LK(a1.z) | (LK(e1.z) << 16), m7 = LK(a1.w) | (LK(e1.w) << 16);
    uint32_t m8 = LK(a2.x) | (LK(e2.x) << 16), m9 = LK(a2.y) | (LK(e2.y) << 16);
    uint32_t mA = LK(a2.z) | (LK(e2.z) << 16), mB = LK(a2.w) | (LK(e2.w) << 16);
    uint32_t mC = LK(a3.x) | (LK(e3.x) << 16), mD = LK(a3.y) | (LK(e3.y) << 16);
    uint32_t mE = LK(a3.z) | (LK(e3.z) << 16), mF = LK(a3.w) | (LK(e3.w) << 16);
#undef LK

    uint32_t s1 = m0 ^ m1 ^ m2, c1 = maj3(m0, m1, m2);
    uint32_t s2 = m3 ^ m4 ^ m5, c2 = maj3(m3, m4, m5);
    uint32_t s3 = s1 ^ s2 ^ m6, c3 = maj3(s1, s2, m6);
    uint32_t a1s = s3 ^ m7,      c4 = s3 & m7;
    uint32_t s4 = c1 ^ c2 ^ c3, c5 = maj3(c1, c2, c3);
    uint32_t a2s = s4 ^ c4,      c6 = s4 & c4;
    uint32_t a4s = c5 ^ c6,      a8s = c5 & c6;
    uint32_t u1 = m8 ^ m9 ^ mA, e1c = maj3(m8, m9, mA);
    uint32_t u2 = mB ^ mC ^ mD, e2c = maj3(mB, mC, mD);
    uint32_t u3 = u1 ^ u2 ^ mE, e3c = maj3(u1, u2, mE);
    uint32_t b1s = u3 ^ mF,      e4c = u3 & mF;
    uint32_t u4 = e1c ^ e2c ^ e3c, e5c = maj3(e1c, e2c, e3c);
    uint32_t b2s = u4 ^ e4c,       e6c = u4 & e4c;
    uint32_t b4s = e5c ^ e6c,      b8s = e5c & e6c;

    uint32_t k  = a1s & b1s;
    uint32_t v0 = a1s ^ b1s;
    uint32_t v1 = a2s ^ b2s ^ k;  k = maj3(a2s, b2s, k);
    uint32_t v2 = a4s ^ b4s ^ k;  k = maj3(a4s, b4s, k);
    uint32_t v3 = a8s ^ b8s ^ k;
    uint32_t v4 = maj3(a8s, b8s, k);

    uint32_t r0 = SHFLX(v0, 1), r1 = SHFLX(v1, 1), r2 = SHFLX(v2, 1),
             r3 = SHFLX(v3, 1), r4 = SHFLX(v4, 1);
    k = v0 & r0;
    uint32_t t0 = v0 ^ r0;
    uint32_t t1 = v1 ^ r1 ^ k;  k = maj3(v1, r1, k);
    uint32_t t2 = v2 ^ r2 ^ k;  k = maj3(v2, r2, k);
    uint32_t t3 = v3 ^ r3 ^ k;  k = maj3(v3, r3, k);
    uint32_t t4 = v4 ^ r4 ^ k;
    uint32_t t5 = maj3(v4, r4, k);

    r0 = SHFLX(t0, 2); r1 = SHFLX(t1, 2); r2 = SHFLX(t2, 2); r3 = SHFLX(t3, 2);
    r4 = SHFLX(t4, 2); uint32_t r5 = SHFLX(t5, 2);
    k = t0 & r0;
    k = maj3(t1, r1, k);
    k = maj3(t2, r2, k);
    k = maj3(t3, r3, k);
    uint32_t segmask = t4 | r4 | t5 | r5 | k;

    uint32_t p  = SHFLX(segmask, 4);
    uint32_t c0 = segmask ^ p, cc1 = segmask & p;
    uint32_t q0 = SHFLX(c0, 8), q1 = SHFLX(cc1, 8);
    k = c0 & q0;
    uint32_t f0 = c0 ^ q0;
    uint32_t f1 = cc1 ^ q1 ^ k;
    uint32_t f2 = maj3(cc1, q1, k);
    uint32_t h0 = SHFLX(f0, 16), h1 = SHFLX(f1, 16), h2 = SHFLX(f2, 16);
    k = f0 & h0;
    uint32_t k2 = maj3(f1, h1, k);
    return f2 | h2 | k2;
}

// Pack x (16 x 16384 floats of {0,1}) into per-position 16-bit batch masks.
__global__ void __launch_bounds__(256) k_pack(const float* __restrict__ x) {
    int j = blockIdx.x * 256 + threadIdx.x;
    float v[16];
#pragma unroll
    for (int b = 0; b < 16; b++) v[b] = x[b * 16384 + j];
    uint32_t m = 0;
#pragma unroll
    for (int b = 0; b < 16; b++)
        m |= (v[b] != 0.0f) ? (1u << b) : 0u;
    g_xbits[j] = (uint16_t)m;
    cudaTriggerProgrammaticLaunchCompletion();
}

// Layer 1: 1024 blocks x 8 warps; warp = ONE dual-pair (8192 pairs).
// Regs capped at 64 (4 blocks/SM = 32 warps/SM): only the A-half is hoisted
// above the PDL sync; the E-half loads are issued while the 32KB TMA table
// fill is in flight (both independent of the table).
__global__ void __launch_bounds__(256, 4) k_l1(const int* __restrict__ idx1) {
    __shared__ __align__(16) uint16_t sx[16400];
    __shared__ __align__(8) uint64_t mbar[1];

    int tid = threadIdx.x;
    int w = tid >> 5, lane = tid & 31;
    int seg = lane >> 2, q = lane & 3;
    uint32_t mb = smem_u32(mbar);
    if (tid == 0)
        asm volatile("mbarrier.init.shared::cta.b64 [%0], 1;" :: "r"(mb) : "memory");

    int pair = blockIdx.x * 8 + w;               // 0..8191
    int laneoff = seg * 64 + q * 16;
    const int4* bA = reinterpret_cast<const int4*>(idx1 + pair * 1024 + laneoff);

    int4 A[4];
#pragma unroll
    for (int i = 0; i < 4; i++) A[i] = __ldcs(bA + i);

    cudaGridDependencySynchronize();             // upstream: k_pack
    __syncthreads();                             // mbarrier init visible
    bulk_fill_issue(sx, g_xbits, mb);            // TMA fill in flight

    int4 E[4];                                   // overlap with the fill
#pragma unroll
    for (int i = 0; i < 4; i++) E[i] = __ldcs(bA + 128 + i);

    mbar_wait(mb, 0);
    __syncthreads();

    uint32_t ge = branch_mask_dual(A, E, sx);
    if (lane == 0)
        reinterpret_cast<uint32_t*>(g_act1)[pair] = ge;
    cudaTriggerProgrammaticLaunchCompletion();
}

// Layer 2 (t==0 only): 128 blocks x 8 warps; warp = one (c,br) dual-pair.
__global__ void __launch_bounds__(256, 4) k_l2(const int* __restrict__ idx2,
                                               float* __restrict__ out) {
    __shared__ __align__(16) uint16_t sx[16400];
    __shared__ __align__(8) uint64_t mbar[1];

    int tid = threadIdx.x;
    int w = tid >> 5, lane = tid & 31;
    int seg = lane >> 2, q = lane & 3;
    uint32_t mb = smem_u32(mbar);
    if (tid == 0)
        asm volatile("mbarrier.init.shared::cta.b64 [%0], 1;" :: "r"(mb) : "memory");

    int pr = (blockIdx.x * 8 + w) * 2;           // even branch id = c*16 + br
    int c = pr >> 4, brA = pr & 15;
    int laneoff = seg * 64 + q * 16;
    const int4* baseA = reinterpret_cast<const int4*>(
        idx2 + (c * 1024 + brA * 8) * 64 + laneoff);

    int4 A[4];
#pragma unroll
    for (int i = 0; i < 4; i++) A[i] = __ldcs(baseA + i);

    cudaGridDependencySynchronize();             // upstream: k_l1
    __syncthreads();
    bulk_fill_issue(sx, g_act1, mb);

    int4 E[4];
#pragma unroll
    for (int i = 0; i < 4; i++) E[i] = __ldcs(baseA + 128 + i);

    mbar_wait(mb, 0);
    __syncthreads();

    uint32_t ge4 = branch_mask_dual(A, E, sx);
    // lanes 0..15 -> batches of branch A; 16..31 -> batches of branch B
    int batch = lane & 15;
    int br = brA + (lane >> 4);
    out[(batch * 128 + c) * 16 + br] = ((ge4 >> lane) & 1u) ? 1.0f : 0.0f;
}

extern "C" void kernel_launch(void* const* d_in, const int* in_sizes, int n_in,
                              void* d_out, int out_size) {
    const float* x = nullptr;
    const int* idxA = nullptr;
    const int* idxB = nullptr;
    for (int i = 0; i < n_in; i++) {
        if (in_sizes[i] == 262144 && !x) {
            x = (const float*)d_in[i];
        } else if (!idxA) {
            idxA = (const int*)d_in[i];
        } else if (!idxB) {
            idxB = (const int*)d_in[i];
        }
    }
    if (!x) { x = (const float*)d_in[0]; idxA = (const int*)d_in[1]; idxB = (const int*)d_in[2]; }

    float* out = (float*)d_out;   // (16, 128, 16) float32

    k_pack<<<64, 256>>>(const_cast<float*>(x));

    cudaLaunchAttribute attr[1];
    attr[0].id = cudaLaunchAttributeProgrammaticStreamSerialization;
    attr[0].val.programmaticStreamSerializationAllowed = 1;

    {
        cudaLaunchConfig_t cfg = {};
        cfg.gridDim = dim3(1024, 1, 1);
        cfg.blockDim = dim3(256, 1, 1);
        cfg.dynamicSmemBytes = 0;
        cfg.stream = 0;
        cfg.attrs = attr;
        cfg.numAttrs = 1;
        cudaLaunchKernelEx(&cfg, k_l1, idxA);
    }
    {
        cudaLaunchConfig_t cfg = {};
        cfg.gridDim = dim3(128, 1, 1);
        cfg.blockDim = dim3(256, 1, 1);
        cfg.dynamicSmemBytes = 0;
        cfg.stream = 0;
        cfg.attrs = attr;
        cfg.numAttrs = 1;
        cudaLaunchKernelEx(&cfg, k_l2, idxB, out);
    }
}